// round 14
// baseline (speedup 1.0000x reference)
#include <cuda_runtime.h>
#include <cstdint>

#define BDIM 16
#define NH 4
#define HD 64
#define CIN 256
#define LLEN 1024
#define NGRP 32
#define GSIZE 8

typedef uint32_t u32;

__device__ __forceinline__ u32 pk(float lo, float hi) {
    u32 r; asm("cvt.rn.bf16x2.f32 %0, %1, %2;" : "=r"(r) : "f"(hi), "f"(lo));
    return r;
}
__device__ __forceinline__ u32 pkh(float lo, float hi) {   // f32x2 -> f16x2
    u32 r; asm("cvt.rn.f16x2.f32 %0, %1, %2;" : "=r"(r) : "f"(hi), "f"(lo));
    return r;
}
__device__ __forceinline__ u32 ex2h(u32 x) {               // 2x exp2 in fp16
    u32 y; asm("ex2.approx.f16x2 %0, %1;" : "=r"(y) : "r"(x)); return y;
}
__device__ __forceinline__ void mma16(float c[4], const u32 a[4], u32 b0, u32 b1) {
    asm volatile("mma.sync.aligned.m16n8k16.row.col.f32.bf16.bf16.f32 "
        "{%0,%1,%2,%3}, {%4,%5,%6,%7}, {%8,%9}, {%0,%1,%2,%3};"
        : "+f"(c[0]), "+f"(c[1]), "+f"(c[2]), "+f"(c[3])
        : "r"(a[0]), "r"(a[1]), "r"(a[2]), "r"(a[3]), "r"(b0), "r"(b1));
}
__device__ __forceinline__ void mma16h(float c[4], const u32 a[4], u32 b0, u32 b1) {
    asm volatile("mma.sync.aligned.m16n8k16.row.col.f32.f16.f16.f32 "
        "{%0,%1,%2,%3}, {%4,%5,%6,%7}, {%8,%9}, {%0,%1,%2,%3};"
        : "+f"(c[0]), "+f"(c[1]), "+f"(c[2]), "+f"(c[3])
        : "r"(a[0]), "r"(a[1]), "r"(a[2]), "r"(a[3]), "r"(b0), "r"(b1));
}
__device__ __forceinline__ void ldsm4(u32 r[4], u32 saddr) {
    asm volatile("ldmatrix.sync.aligned.m8n8.x4.shared.b16 {%0,%1,%2,%3}, [%4];"
        : "=r"(r[0]), "=r"(r[1]), "=r"(r[2]), "=r"(r[3]) : "r"(saddr));
}
__device__ __forceinline__ u32 s2u(const void* p) {
    return (u32)__cvta_generic_to_shared(p);
}
__device__ __forceinline__ u32 ldsm_off(int lane, int strideU32) {
    return (u32)((((lane & 7) + ((lane >> 4) & 1) * 8) * strideU32 + ((lane >> 3) & 1) * 4) * 4);
}
__device__ __forceinline__ void cpa16(u32 dst, const void* src) {
    asm volatile("cp.async.cg.shared.global [%0], [%1], 16;" :: "r"(dst), "l"(src));
}
__device__ __forceinline__ void cpa32(u32 dst, const u32* src) {
    cpa16(dst, src); cpa16(dst + 16, src + 4);
}
#define CP_COMMIT() asm volatile("cp.async.commit_group;" ::: "memory")
#define CP_WAIT1()  asm volatile("cp.async.wait_group 1;" ::: "memory")
#define CP_WAIT2()  asm volatile("cp.async.wait_group 2;" ::: "memory")

// Scratch (u32 = packed bf16x2 / f16x2)
__device__ u32 g_h2[BDIM * 128 * LLEN];   // [b][c2][l] bf16x2
__device__ u32 g_w2[4 * 256 * 128];       // [w][e][c2] bf16x2
__device__ u32 g_q32[64 * LLEN * 32];     // [bn][l][d2] bf16x2 (pre-scaled 0.125*log2e)
__device__ u32 g_k32[64 * LLEN * 32];     // [bn][l][d2] bf16x2
__device__ u32 g_v32[BDIM * CIN * 512];   // [b][e][l2]  f16x2
__device__ u32 g_o32[64 * LLEN * 32];     // [bn][l][d2] bf16x2

// ---------------------------------------------------------------------------
// GroupNorm -> packed bf16 h [b][c2][l]
// ---------------------------------------------------------------------------
__global__ __launch_bounds__(256) void gn_kernel(const float* __restrict__ x,
                                                 const float* __restrict__ gamma,
                                                 const float* __restrict__ beta) {
    int bg = blockIdx.x;
    int b = bg / NGRP, g = bg % NGRP;
    const int N = GSIZE * LLEN;
    size_t base = ((size_t)b * CIN + (size_t)g * GSIZE) * LLEN;
    int tid = threadIdx.x;
    const float4* x4 = (const float4*)(x + base);
    float4 vals[8];
    float sum = 0.f, sumsq = 0.f;
#pragma unroll
    for (int r = 0; r < 8; r++) {
        float4 v = x4[r * 256 + tid];
        vals[r] = v;
        sum += v.x + v.y + v.z + v.w;
        sumsq += v.x * v.x + v.y * v.y + v.z * v.z + v.w * v.w;
    }
#pragma unroll
    for (int off = 16; off; off >>= 1) {
        sum += __shfl_xor_sync(0xffffffffu, sum, off);
        sumsq += __shfl_xor_sync(0xffffffffu, sumsq, off);
    }
    __shared__ float wsum[8], wsq[8], s_mean, s_rstd;
    if ((tid & 31) == 0) { wsum[tid >> 5] = sum; wsq[tid >> 5] = sumsq; }
    __syncthreads();
    if (tid == 0) {
        float s = 0.f, q = 0.f;
#pragma unroll
        for (int i = 0; i < 8; i++) { s += wsum[i]; q += wsq[i]; }
        float mean = s / (float)N;
        s_mean = mean;
        s_rstd = rsqrtf(q / (float)N - mean * mean + 1e-5f);
    }
    __syncthreads();
    float mean = s_mean, rstd = s_rstd;
#pragma unroll
    for (int rp = 0; rp < 4; rp++) {
        int c0 = g * GSIZE + 2 * rp;
        float ga0 = gamma[c0] * rstd, be0 = beta[c0];
        float ga1 = gamma[c0 + 1] * rstd, be1 = beta[c0 + 1];
        float4 a = vals[2 * rp], bb = vals[2 * rp + 1];
        a.x = (a.x - mean) * ga0 + be0; a.y = (a.y - mean) * ga0 + be0;
        a.z = (a.z - mean) * ga0 + be0; a.w = (a.w - mean) * ga0 + be0;
        bb.x = (bb.x - mean) * ga1 + be1; bb.y = (bb.y - mean) * ga1 + be1;
        bb.z = (bb.z - mean) * ga1 + be1; bb.w = (bb.w - mean) * ga1 + be1;
        *(uint4*)(g_h2 + ((size_t)b * 128 + g * 4 + rp) * LLEN + tid * 4) =
            make_uint4(pk(a.x, bb.x), pk(a.y, bb.y), pk(a.z, bb.z), pk(a.w, bb.w));
    }
}

// ---------------------------------------------------------------------------
// Weight pre-pack: fp32 [e][c] -> bf16x2 [e][c2]
// ---------------------------------------------------------------------------
__global__ __launch_bounds__(256) void wcvt(const float* __restrict__ wq,
                                            const float* __restrict__ wk,
                                            const float* __restrict__ wv,
                                            const float* __restrict__ wp) {
    int w = blockIdx.x >> 5, wb = blockIdx.x & 31;
    const float* W = (w == 0) ? wq : (w == 1) ? wk : (w == 2) ? wv : wp;
    int o = (wb * 256 + threadIdx.x) * 4;
    int e = o >> 7, c2 = o & 127;
    const float* s = W + (size_t)e * CIN + c2 * 2;
    float4 f0 = *(const float4*)s, f1 = *(const float4*)(s + 4);
    *(uint4*)(g_w2 + w * 32768 + o) =
        make_uint4(pk(f0.x, f0.y), pk(f0.z, f0.w), pk(f1.x, f1.y), pk(f1.z, f1.w));
}

// ---------------------------------------------------------------------------
// Fused QKV GEMM, 4-stage cp.async pipeline. z: 0=q (scaled), 1=k, 2=v (fp16 out).
// ---------------------------------------------------------------------------
__global__ __launch_bounds__(256, 2) void gemm_qkv(const float* __restrict__ bq,
                                                   const float* __restrict__ bk,
                                                   const float* __restrict__ bv) {
    extern __shared__ u32 dsm[];
    u32* sH = dsm;            // 4 * 2176
    u32* sW = dsm + 8704;     // 4 * 2560
    int z = blockIdx.z;
    const u32* Wg = g_w2 + z * 32768;
    const float* Bi = (z == 0) ? bq : (z == 1) ? bk : bv;
    int b = blockIdx.y >> 1, e0 = (blockIdx.y & 1) * 128, l0 = blockIdx.x * 128;
    const u32* hb = g_h2 + (size_t)b * 128 * LLEN;

    int tid = threadIdx.x, lane = tid & 31, wid = tid >> 5;
    int g = lane >> 2, q = lane & 3, lw = wid * 16;
    int hrow = tid >> 4, hsg = (tid & 15) * 8;
    int we = tid >> 1, wsg = (tid & 1) * 8;

    auto stage = [&](int cc, int buf) {
        cpa32(s2u(&sH[buf * 2176 + hrow * 136 + hsg]),
              hb + (size_t)(cc * 16 + hrow) * LLEN + l0 + hsg);
        cpa32(s2u(&sW[buf * 2560 + we * 20 + wsg]),
              Wg + (size_t)(e0 + we) * 128 + cc * 16 + wsg);
    };

    float oc[16][4];
#pragma unroll
    for (int nb = 0; nb < 16; nb++)
#pragma unroll
        for (int j = 0; j < 4; j++) oc[nb][j] = 0.f;

    stage(0, 0); CP_COMMIT();
    stage(1, 1); CP_COMMIT();
    stage(2, 2); CP_COMMIT();
    for (int cc = 0; cc < 8; cc++) {
        CP_WAIT2();
        __syncthreads();
        if (cc < 5) { stage(cc + 3, (cc + 3) & 3); }
        CP_COMMIT();
        int buf = cc & 3;
        const u32* sHb = sH + buf * 2176;
        const u32* sWb = sW + buf * 2560;
        if (z < 2) {
            u32 wbase = s2u(sWb) + ldsm_off(lane, 20);
#pragma unroll
            for (int ks = 0; ks < 2; ks++) {
                int r0 = (q + 8 * ks) * 136, r1 = (q + 4 + 8 * ks) * 136;
                u32 a[4] = {sHb[r0 + lw + g], sHb[r0 + lw + g + 8],
                            sHb[r1 + lw + g], sHb[r1 + lw + g + 8]};
#pragma unroll
                for (int p = 0; p < 8; p++) {
                    u32 bfr[4];
                    ldsm4(bfr, wbase + p * 16 * 20 * 4 + ks * 32);
                    mma16(oc[2 * p], a, bfr[0], bfr[1]);
                    mma16(oc[2 * p + 1], a, bfr[2], bfr[3]);
                }
            }
        } else {
#pragma unroll
            for (int ks = 0; ks < 2; ks++) {
                int ra = (lw + g) * 20 + 8 * ks, rb8 = (lw + g + 8) * 20 + 8 * ks;
                u32 a[4] = {sWb[ra + q], sWb[rb8 + q], sWb[ra + q + 4], sWb[rb8 + q + 4]};
                int k0r = (q + 8 * ks) * 136, k1r = (q + 4 + 8 * ks) * 136;
#pragma unroll
                for (int nb = 0; nb < 16; nb++)
                    mma16(oc[nb], a, sHb[k0r + nb * 8 + g], sHb[k1r + nb * 8 + g]);
            }
        }
    }

    if (z < 2) {
        // q path pre-scaled by 0.125*log2(e) so softmax is a bare ex2
        float sc = z ? 1.f : 0.1803368801111244f;
        u32* Out = z ? g_k32 : g_q32;
#pragma unroll
        for (int nb = 0; nb < 16; nb++) {
            int e = e0 + nb * 8 + 2 * q;
            float bi0 = Bi[e], bi1 = Bi[e + 1];
            int head = e >> 6, d2 = (e & 63) >> 1;
            u32* base = Out + (((size_t)(b * NH + head) * LLEN) + l0 + lw + g) * 32 + d2;
            base[0]      = pk((oc[nb][0] + bi0) * sc, (oc[nb][1] + bi1) * sc);
            base[8 * 32] = pk((oc[nb][2] + bi0) * sc, (oc[nb][3] + bi1) * sc);
        }
    } else {
        int e = e0 + lw + g;
        float bi0 = Bi[e], bi1 = Bi[e + 8];
        u32* ob = g_v32 + ((size_t)b * CIN + e) * 512 + (l0 >> 1);
#pragma unroll
        for (int nb = 0; nb < 16; nb++) {
            ob[nb * 4 + q]           = pkh(oc[nb][0] + bi0, oc[nb][1] + bi0);
            ob[8 * 512 + nb * 4 + q] = pkh(oc[nb][2] + bi1, oc[nb][3] + bi1);
        }
    }
}

// ---------------------------------------------------------------------------
// flash attention: 256 q-rows/block, 128-m pipeline stages (two 64-m
// sub-tiles per stage -> half the barrier/wait count). S-mma bf16; softmax
// via ex2.approx.f16x2 feeding fp16 O-mma; denominators via ones-column mma.
// dyn smem: sQ 2x[128][36], then 3 stages x 2 subs x (sK [64][36] | sV [64][36]).
// ---------------------------------------------------------------------------
__global__ __launch_bounds__(256, 1) void attn_mma() {
    extern __shared__ u32 dsm[];
    u32* sQ = dsm;             // 2 * 4608
    u32* sKV = dsm + 9216;     // 3 * 9216

    int tid = threadIdx.x, lane = tid & 31, wid = tid >> 5;
    int g = lane >> 2, q = lane & 3, lw = wid * 16;
    int l0 = blockIdx.x * 256, bn = blockIdx.y;
    const u32* Qg = g_q32 + (size_t)bn * LLEN * 32;
    const u32* Kg = g_k32 + (size_t)bn * LLEN * 32;
    const u32* Vg = g_v32 + (size_t)bn * 64 * 512;
    u32* Og = g_o32 + (size_t)bn * LLEN * 32;

    const u32 ones = (g == 0) ? 0x3C003C00u : 0u;   // fp16 (1,1) at n=0

    {   // group 0: both Q tiles
        int l = tid >> 1, seg = (tid & 1) * 16;
        const u32* srcA = Qg + (size_t)(l0 + l) * 32 + seg;
        u32 dstA = s2u(&sQ[l * 36 + seg]);
        cpa16(dstA, srcA); cpa16(dstA + 16, srcA + 4);
        cpa16(dstA + 32, srcA + 8); cpa16(dstA + 48, srcA + 12);
        const u32* srcB = Qg + (size_t)(l0 + 128 + l) * 32 + seg;
        u32 dstB = s2u(&sQ[4608 + l * 36 + seg]);
        cpa16(dstB, srcB); cpa16(dstB + 16, srcB + 4);
        cpa16(dstB + 32, srcB + 8); cpa16(dstB + 48, srcB + 12);
    }
    CP_COMMIT();

    int row = tid >> 2, seg = (tid & 3) * 8;
    auto stage = [&](int it8, int buf) {   // loads 128 m-rows (2 sub-tiles)
        int m0 = it8 * 128;
        u32 base = s2u(&sKV[buf * 9216]);
#pragma unroll
        for (int sub = 0; sub < 2; sub++) {
            int ms = m0 + sub * 64;
            cpa32(base + (sub * 4608 + row * 36 + seg) * 4,
                  Kg + (size_t)(ms + row) * 32 + seg);
            cpa32(base + (sub * 4608 + 2304 + row * 36 + seg) * 4,
                  Vg + (size_t)row * 512 + (ms >> 1) + seg);
        }
    };
    stage(0, 0); CP_COMMIT();
    stage(1, 1); CP_COMMIT();

    CP_WAIT2();   // Q group done
    __syncthreads();
    u32 qaA[4][4], qaB[4][4];
#pragma unroll
    for (int ks = 0; ks < 4; ks++) {
        int ra = (lw + g) * 36, rb = (lw + g + 8) * 36;
        qaA[ks][0] = sQ[ra + q + 8 * ks];
        qaA[ks][1] = sQ[rb + q + 8 * ks];
        qaA[ks][2] = sQ[ra + q + 4 + 8 * ks];
        qaA[ks][3] = sQ[rb + q + 4 + 8 * ks];
        qaB[ks][0] = sQ[4608 + ra + q + 8 * ks];
        qaB[ks][1] = sQ[4608 + rb + q + 8 * ks];
        qaB[ks][2] = sQ[4608 + ra + q + 4 + 8 * ks];
        qaB[ks][3] = sQ[4608 + rb + q + 4 + 8 * ks];
    }

    u32 fro = ldsm_off(lane, 36);
    float ocA[8][4], ocB[8][4];
    float dnaA[4], dnaB[4];
#pragma unroll
    for (int nb = 0; nb < 8; nb++)
#pragma unroll
        for (int j = 0; j < 4; j++) { ocA[nb][j] = 0.f; ocB[nb][j] = 0.f; }
#pragma unroll
    for (int j = 0; j < 4; j++) { dnaA[j] = 0.f; dnaB[j] = 0.f; }

    for (int it8 = 0; it8 < 8; it8++) {
        CP_WAIT1();
        __syncthreads();
        if (it8 < 6) { stage(it8 + 2, (it8 + 2) % 3); }
        CP_COMMIT();           // empty on tail keeps the wait invariant
        u32 sbase = s2u(&sKV[(it8 % 3) * 9216]);

#pragma unroll
        for (int sub = 0; sub < 2; sub++) {
            u32 kbase = sbase + sub * 4608 * 4 + fro;
            u32 vbase = kbase + 2304 * 4;

            float scA[8][4], scB[8][4];
#pragma unroll
            for (int nb = 0; nb < 8; nb++)
#pragma unroll
                for (int j = 0; j < 4; j++) { scA[nb][j] = 0.f; scB[nb][j] = 0.f; }

            u32 vfr[4][4][4];   // prefetched V b-frags [ks][p]
#pragma unroll
            for (int ks = 0; ks < 4; ks++)
#pragma unroll
                for (int p = 0; p < 4; p++) {
                    u32 bfr[4];
                    ldsm4(bfr, kbase + p * 16 * 36 * 4 + ks * 32);
                    mma16(scA[2 * p], qaA[ks], bfr[0], bfr[1]);
                    mma16(scA[2 * p + 1], qaA[ks], bfr[2], bfr[3]);
                    mma16(scB[2 * p], qaB[ks], bfr[0], bfr[1]);
                    mma16(scB[2 * p + 1], qaB[ks], bfr[2], bfr[3]);
                }
#pragma unroll
            for (int ks = 0; ks < 4; ks++)
#pragma unroll
                for (int p = 0; p < 4; p++)
                    ldsm4(vfr[ks][p], vbase + p * 16 * 36 * 4 + ks * 32);

            // --- tile A: softmax (fp16 ex2 pairs) + dn-mma + O-mma ---
            u32 paA[4][4];
#pragma unroll
            for (int ks = 0; ks < 4; ks++) {
                paA[ks][0] = ex2h(pkh(scA[2 * ks][0], scA[2 * ks][1]));
                paA[ks][1] = ex2h(pkh(scA[2 * ks][2], scA[2 * ks][3]));
                paA[ks][2] = ex2h(pkh(scA[2 * ks + 1][0], scA[2 * ks + 1][1]));
                paA[ks][3] = ex2h(pkh(scA[2 * ks + 1][2], scA[2 * ks + 1][3]));
            }
#pragma unroll
            for (int ks = 0; ks < 4; ks++) {
                mma16h(dnaA, paA[ks], ones, ones);
#pragma unroll
                for (int p = 0; p < 4; p++) {
                    mma16h(ocA[2 * p], paA[ks], vfr[ks][p][0], vfr[ks][p][1]);
                    mma16h(ocA[2 * p + 1], paA[ks], vfr[ks][p][2], vfr[ks][p][3]);
                }
            }

            // --- tile B ---
            u32 paB[4][4];
#pragma unroll
            for (int ks = 0; ks < 4; ks++) {
                paB[ks][0] = ex2h(pkh(scB[2 * ks][0], scB[2 * ks][1]));
                paB[ks][1] = ex2h(pkh(scB[2 * ks][2], scB[2 * ks][3]));
                paB[ks][2] = ex2h(pkh(scB[2 * ks + 1][0], scB[2 * ks + 1][1]));
                paB[ks][3] = ex2h(pkh(scB[2 * ks + 1][2], scB[2 * ks + 1][3]));
            }
#pragma unroll
            for (int ks = 0; ks < 4; ks++) {
                mma16h(dnaB, paB[ks], ones, ones);
#pragma unroll
                for (int p = 0; p < 4; p++) {
                    mma16h(ocB[2 * p], paB[ks], vfr[ks][p][0], vfr[ks][p][1]);
                    mma16h(ocB[2 * p + 1], paB[ks], vfr[ks][p][2], vfr[ks][p][3]);
                }
            }
        }
    }

    // dn sums live in q==0 lane (column 0 of c-frag); broadcast within group
    int src = lane & 28;
    float dA0 = __shfl_sync(0xffffffffu, dnaA[0], src);
    float dA1 = __shfl_sync(0xffffffffu, dnaA[2], src);
    float dB0 = __shfl_sync(0xffffffffu, dnaB[0], src);
    float dB1 = __shfl_sync(0xffffffffu, dnaB[2], src);
    float iA0 = 1.f / dA0, iA1 = 1.f / dA1;
    float iB0 = 1.f / dB0, iB1 = 1.f / dB1;

    u32* a0 = Og + (size_t)(l0 + lw + g) * 32;
    u32* a1 = a0 + 8 * 32;
    u32* b0 = Og + (size_t)(l0 + 128 + lw + g) * 32;
    u32* b1 = b0 + 8 * 32;
#pragma unroll
    for (int nb = 0; nb < 8; nb++) {
        a0[nb * 4 + q] = pk(ocA[nb][0] * iA0, ocA[nb][1] * iA0);
        a1[nb * 4 + q] = pk(ocA[nb][2] * iA1, ocA[nb][3] * iA1);
        b0[nb * 4 + q] = pk(ocB[nb][0] * iB0, ocB[nb][1] * iB0);
        b1[nb * 4 + q] = pk(ocB[nb][2] * iB1, ocB[nb][3] * iB1);
    }
}

// ---------------------------------------------------------------------------
// Proj GEMM: fp32 out with bias + residual, 4-stage cp.async pipeline.
// ---------------------------------------------------------------------------
__global__ __launch_bounds__(256, 2) void gemm_proj(const float* __restrict__ Bi,
                                                    const float* __restrict__ resid,
                                                    float* __restrict__ Out) {
    extern __shared__ u32 dsm[];
    u32* sW = dsm;            // 4 * 2560
    u32* sO = dsm + 10240;    // 4 * 2560
    const u32* Wg = g_w2 + 3 * 32768;
    int b = blockIdx.y >> 1, e0 = (blockIdx.y & 1) * 128, l0 = blockIdx.x * 128;

    int tid = threadIdx.x, lane = tid & 31, wid = tid >> 5;
    int g = lane >> 2, q = lane & 3, lw = wid * 16;
    int we = tid >> 1, wsg = (tid & 1) * 8;

    auto stage = [&](int cc, int buf) {
        cpa32(s2u(&sW[buf * 2560 + we * 20 + wsg]),
              Wg + (size_t)(e0 + we) * 128 + cc * 16 + wsg);
        int c0 = cc * 32, head = c0 >> 6, d2b = (c0 & 63) >> 1;
        cpa32(s2u(&sO[buf * 2560 + we * 20 + wsg]),
              g_o32 + (((size_t)(b * NH + head) * LLEN) + l0 + we) * 32 + d2b + wsg);
    };

    float oc[16][4];
#pragma unroll
    for (int nb = 0; nb < 16; nb++)
#pragma unroll
        for (int j = 0; j < 4; j++) oc[nb][j] = 0.f;

    stage(0, 0); CP_COMMIT();
    stage(1, 1); CP_COMMIT();
    stage(2, 2); CP_COMMIT();
    for (int cc = 0; cc < 8; cc++) {
        CP_WAIT2();
        __syncthreads();
        if (cc < 5) { stage(cc + 3, (cc + 3) & 3); }
        CP_COMMIT();
        int buf = cc & 3;
        const u32* sWb = sW + buf * 2560;
        u32 obase = s2u(sO + buf * 2560) + ldsm_off(lane, 20);
#pragma unroll
        for (int ks = 0; ks < 2; ks++) {
            int ra = (lw + g) * 20 + 8 * ks, rb8 = (lw + g + 8) * 20 + 8 * ks;
            u32 a[4] = {sWb[ra + q], sWb[rb8 + q], sWb[ra + q + 4], sWb[rb8 + q + 4]};
#pragma unroll
            for (int p = 0; p < 8; p++) {
                u32 bfr[4];
                ldsm4(bfr, obase + p * 16 * 20 * 4 + ks * 32);
                mma16(oc[2 * p], a, bfr[0], bfr[1]);
                mma16(oc[2 * p + 1], a, bfr[2], bfr[3]);
            }
        }
    }
    int r0 = e0 + lw + g, r1 = r0 + 8;
    float bi0 = Bi[r0], bi1 = Bi[r1];
    float* ob = Out + (size_t)b * CIN * LLEN;
    const float* rb = resid + (size_t)b * CIN * LLEN;
#pragma unroll
    for (int nb = 0; nb < 16; nb++) {
        int col = l0 + nb * 8 + 2 * q;
        float2 x0 = *(const float2*)(rb + (size_t)r0 * LLEN + col);
        float2 x1 = *(const float2*)(rb + (size_t)r1 * LLEN + col);
        *(float2*)(ob + (size_t)r0 * LLEN + col) =
            make_float2(oc[nb][0] + bi0 + x0.x, oc[nb][1] + bi0 + x0.y);
        *(float2*)(ob + (size_t)r1 * LLEN + col) =
            make_float2(oc[nb][2] + bi1 + x1.x, oc[nb][3] + bi1 + x1.y);
    }
}

// ---------------------------------------------------------------------------
// Launch
// ---------------------------------------------------------------------------
extern "C" void kernel_launch(void* const* d_in, const int* in_sizes, int n_in,
                              void* d_out, int out_size) {
    const float* x     = (const float*)d_in[0];
    const float* gamma = (const float*)d_in[1];
    const float* beta  = (const float*)d_in[2];
    const float* bq    = (const float*)d_in[4];
    const float* bk    = (const float*)d_in[6];
    const float* bv    = (const float*)d_in[8];
    const float* bproj = (const float*)d_in[10];
    float* out = (float*)d_out;

    gn_kernel<<<BDIM * NGRP, 256>>>(x, gamma, beta);
    wcvt<<<128, 256>>>((const float*)d_in[3], (const float*)d_in[5],
                       (const float*)d_in[7], (const float*)d_in[9]);

    int qkv_smem = (8704 + 10240) * 4;   // 75776
    cudaFuncSetAttribute(gemm_qkv, cudaFuncAttributeMaxDynamicSharedMemorySize, qkv_smem);
    gemm_qkv<<<dim3(LLEN / 128, 2 * BDIM, 3), 256, qkv_smem>>>(bq, bk, bv);

    int attn_smem = (9216 + 3 * 9216) * 4;   // 147456
    cudaFuncSetAttribute(attn_mma, cudaFuncAttributeMaxDynamicSharedMemorySize, attn_smem);
    attn_mma<<<dim3(LLEN / 256, BDIM * NH), 256, attn_smem>>>();

    int proj_smem = 20480 * 4;           // 81920
    cudaFuncSetAttribute(gemm_proj, cudaFuncAttributeMaxDynamicSharedMemorySize, proj_smem);
    gemm_proj<<<dim3(LLEN / 128, 2 * BDIM), 256, proj_smem>>>(bproj, x, out);
}